// round 1
// baseline (speedup 1.0000x reference)
#include <cuda_runtime.h>
#include <math.h>
#include <stdint.h>

#define CDIM 512
#define HDIM 1024
#define KW 5
#define BSEG 8
#define EPSV 1e-5f
#define MAXN 24576

// ---------------- scratch (static device globals; no allocations) ----------
__device__ float g_xn[(size_t)MAXN * CDIM];      // normalized feats [N, C]
__device__ float g_state[(size_t)MAXN * HDIM];   // gelu(xn @ W_in^T) [N, H]
__device__ float g_mixed[(size_t)MAXN * HDIM];   // gelu(conv(state)) [N, H]
__device__ float g_sum[BSEG], g_sumsq[BSEG];
__device__ float g_mean[BSEG], g_rstd[BSEG];
__device__ float g_colsum[BSEG * CDIM];          // sum over length of xn
__device__ float g_gate[BSEG * CDIM];
__device__ float g_wc[KW * HDIM];                // combined fwd/bwd dw weights

__device__ __forceinline__ float gelu_exact(float x) {
    return 0.5f * x * (1.0f + erff(x * 0.7071067811865475f));
}

// ---------------- prep: zero accumulators + combined conv weights ----------
__global__ void prep_kernel(const float* __restrict__ fwd_w,
                            const float* __restrict__ bwd_w) {
    int i = blockIdx.x * blockDim.x + threadIdx.x;
    if (i < BSEG) { g_sum[i] = 0.f; g_sumsq[i] = 0.f; }
    if (i < BSEG * CDIM) g_colsum[i] = 0.f;
    if (i < KW * HDIM) {
        int k = i / HDIM, h = i % HDIM;
        g_wc[i] = 0.5f * (fwd_w[h * KW + k] + bwd_w[h * KW + (KW - 1 - k)]);
    }
}

// ---------------- per-segment sum / sumsq ----------------------------------
__global__ void reduce_kernel(const float* __restrict__ feat,
                              const int* __restrict__ offset) {
    int b = blockIdx.y;
    int start = b ? offset[b - 1] : 0;
    long base4 = (long)start * (CDIM / 4);
    long end4  = (long)offset[b] * (CDIM / 4);
    const float4* f4 = (const float4*)feat;
    float s = 0.f, s2 = 0.f;
    long i = base4 + (long)blockIdx.x * (blockDim.x * 4) + threadIdx.x;
#pragma unroll
    for (int it = 0; it < 4; ++it) {
        if (i < end4) {
            float4 v = f4[i];
            s  += v.x + v.y + v.z + v.w;
            s2 += v.x * v.x + v.y * v.y + v.z * v.z + v.w * v.w;
        }
        i += blockDim.x;
    }
    unsigned m = 0xffffffffu;
    for (int o = 16; o; o >>= 1) {
        s  += __shfl_down_sync(m, s, o);
        s2 += __shfl_down_sync(m, s2, o);
    }
    __shared__ float sh[2][8];
    int lane = threadIdx.x & 31, w = threadIdx.x >> 5;
    if (lane == 0) { sh[0][w] = s; sh[1][w] = s2; }
    __syncthreads();
    if (w == 0) {
        s  = lane < 8 ? sh[0][lane] : 0.f;
        s2 = lane < 8 ? sh[1][lane] : 0.f;
        for (int o = 4; o; o >>= 1) {
            s  += __shfl_down_sync(m, s, o);
            s2 += __shfl_down_sync(m, s2, o);
        }
        if (lane == 0) { atomicAdd(&g_sum[b], s); atomicAdd(&g_sumsq[b], s2); }
    }
}

__global__ void finalize_kernel(const int* __restrict__ offset) {
    int b = threadIdx.x;
    if (b < BSEG) {
        int start = b ? offset[b - 1] : 0;
        int cnt = offset[b] - start;
        float denom = (float)cnt * (float)CDIM;
        float mean = g_sum[b] / denom;
        float var = g_sumsq[b] / denom - mean * mean;
        g_mean[b] = mean;
        g_rstd[b] = rsqrtf(var + EPSV);
    }
}

// ---------------- normalize + per-channel column sums ----------------------
// grid (ceil(max_len/32), BSEG), block 128 (each thread owns 4 channels)
__global__ void norm_kernel(const float* __restrict__ feat,
                            const int* __restrict__ offset,
                            const float* __restrict__ nw,
                            const float* __restrict__ nb) {
    int b = blockIdx.y;
    int start = b ? offset[b - 1] : 0;
    int end = offset[b];
    int row0 = start + blockIdx.x * 32;
    if (row0 >= end) return;
    int tid = threadIdx.x;
    float4 w  = ((const float4*)nw)[tid];
    float4 bb = ((const float4*)nb)[tid];
    float mean = g_mean[b], rstd = g_rstd[b];
    float4 acc = make_float4(0.f, 0.f, 0.f, 0.f);
    int rend = min(end, row0 + 32);
    for (int r = row0; r < rend; ++r) {
        float4 v = ((const float4*)feat)[(long)r * (CDIM / 4) + tid];
        float4 x;
        x.x = (v.x - mean) * rstd * w.x + bb.x;
        x.y = (v.y - mean) * rstd * w.y + bb.y;
        x.z = (v.z - mean) * rstd * w.z + bb.z;
        x.w = (v.w - mean) * rstd * w.w + bb.w;
        ((float4*)g_xn)[(long)r * (CDIM / 4) + tid] = x;
        acc.x += x.x; acc.y += x.y; acc.z += x.z; acc.w += x.w;
    }
    float* cs = &g_colsum[b * CDIM + tid * 4];
    atomicAdd(cs + 0, acc.x);
    atomicAdd(cs + 1, acc.y);
    atomicAdd(cs + 2, acc.z);
    atomicAdd(cs + 3, acc.w);
}

// ---------------- gate: sigmoid((colsum/cnt) @ gate_w^T) -------------------
// grid (C/128, BSEG), block 128
__global__ void gate_kernel(const float* __restrict__ gw,
                            const int* __restrict__ offset) {
    __shared__ float ms[CDIM];
    int b = blockIdx.y;
    int start = b ? offset[b - 1] : 0;
    float inv = 1.0f / (float)(offset[b] - start);
    for (int i = threadIdx.x; i < CDIM; i += blockDim.x)
        ms[i] = g_colsum[b * CDIM + i] * inv;
    __syncthreads();
    int c = blockIdx.x * blockDim.x + threadIdx.x;
    const float4* gr = (const float4*)(gw + (size_t)c * CDIM);
    float acc = 0.f;
#pragma unroll 4
    for (int k = 0; k < CDIM / 4; ++k) {
        float4 v = gr[k];
        acc += v.x * ms[4 * k] + v.y * ms[4 * k + 1] + v.z * ms[4 * k + 2] + v.w * ms[4 * k + 3];
    }
    g_gate[b * CDIM + c] = 1.0f / (1.0f + expf(-acc));
}

// ---------------- SGEMM1: g_state = gelu(g_xn @ W_in^T) --------------------
// A = g_xn [M, C], B = W [H, C] (both K-contiguous), 128x128x8, 8x8/thread
__global__ __launch_bounds__(256) void gemm1_kernel(const float* __restrict__ W, int M) {
    __shared__ float As[8][128];
    __shared__ float Bs[8][128];
    const int tid = threadIdx.x;
    const int tx = tid & 15, ty = tid >> 4;
    const int lr = tid >> 1, lc = (tid & 1) * 4;
    const int mBase = blockIdx.y * 128, nBase = blockIdx.x * 128;
    float acc[8][8];
#pragma unroll
    for (int i = 0; i < 8; ++i)
#pragma unroll
        for (int j = 0; j < 8; ++j) acc[i][j] = 0.f;
    const bool aok = (mBase + lr) < M;
    const float* Aptr = g_xn + (size_t)(mBase + lr) * CDIM + lc;
    const float* Bptr = W + (size_t)(nBase + lr) * CDIM + lc;
    for (int kt = 0; kt < CDIM; kt += 8) {
        float4 av = aok ? *(const float4*)(Aptr + kt) : make_float4(0, 0, 0, 0);
        float4 bv = *(const float4*)(Bptr + kt);
        As[lc + 0][lr] = av.x; As[lc + 1][lr] = av.y; As[lc + 2][lr] = av.z; As[lc + 3][lr] = av.w;
        Bs[lc + 0][lr] = bv.x; Bs[lc + 1][lr] = bv.y; Bs[lc + 2][lr] = bv.z; Bs[lc + 3][lr] = bv.w;
        __syncthreads();
#pragma unroll
        for (int kk = 0; kk < 8; ++kk) {
            float a[8], bfr[8];
            *(float4*)&a[0]   = *(const float4*)&As[kk][ty * 4];
            *(float4*)&a[4]   = *(const float4*)&As[kk][64 + ty * 4];
            *(float4*)&bfr[0] = *(const float4*)&Bs[kk][tx * 4];
            *(float4*)&bfr[4] = *(const float4*)&Bs[kk][64 + tx * 4];
#pragma unroll
            for (int i = 0; i < 8; ++i)
#pragma unroll
                for (int j = 0; j < 8; ++j) acc[i][j] += a[i] * bfr[j];
        }
        __syncthreads();
    }
#pragma unroll
    for (int i = 0; i < 8; ++i) {
        int row = mBase + ((i < 4) ? (ty * 4 + i) : (64 + ty * 4 + i - 4));
        if (row >= M) continue;
        float4 v0, v1;
        v0.x = gelu_exact(acc[i][0]); v0.y = gelu_exact(acc[i][1]);
        v0.z = gelu_exact(acc[i][2]); v0.w = gelu_exact(acc[i][3]);
        v1.x = gelu_exact(acc[i][4]); v1.y = gelu_exact(acc[i][5]);
        v1.z = gelu_exact(acc[i][6]); v1.w = gelu_exact(acc[i][7]);
        *(float4*)&g_state[(size_t)row * HDIM + nBase + tx * 4] = v0;
        *(float4*)&g_state[(size_t)row * HDIM + nBase + 64 + tx * 4] = v1;
    }
}

// ---------------- depthwise conv (fwd+bwd combined) + gelu -----------------
// grid (N, H/256), block 256
__global__ void conv_kernel(const int* __restrict__ offset, int N) {
    int n = blockIdx.x;
    int h = blockIdx.y * 256 + threadIdx.x;
    int b = 0;
    while (b < BSEG - 1 && n >= offset[b]) ++b;
    int start = b ? offset[b - 1] : 0;
    int end = offset[b];
    float acc = 0.f;
#pragma unroll
    for (int k = 0; k < KW; ++k) {
        int r = n - (KW / 2) + k;
        if (r >= start && r < end)
            acc += g_wc[k * HDIM + h] * g_state[(size_t)r * HDIM + h];
    }
    g_mixed[(size_t)n * HDIM + h] = gelu_exact(acc);
}

// ---------------- SGEMM2 + fused epilogue ----------------------------------
// out[n][c] = feat[n][c] + fw * gate[bid(n)][c] * (mixed[n] . W_out[c])
__global__ __launch_bounds__(256) void gemm2_kernel(const float* __restrict__ W,
                                                    const float* __restrict__ feat,
                                                    const int* __restrict__ offset,
                                                    const float* __restrict__ fwp,
                                                    float* __restrict__ out, int M) {
    __shared__ float As[8][128];
    __shared__ float Bs[8][128];
    const int tid = threadIdx.x;
    const int tx = tid & 15, ty = tid >> 4;
    const int lr = tid >> 1, lc = (tid & 1) * 4;
    const int mBase = blockIdx.y * 128, nBase = blockIdx.x * 128;
    float acc[8][8];
#pragma unroll
    for (int i = 0; i < 8; ++i)
#pragma unroll
        for (int j = 0; j < 8; ++j) acc[i][j] = 0.f;
    const bool aok = (mBase + lr) < M;
    const float* Aptr = g_mixed + (size_t)(mBase + lr) * HDIM + lc;
    const float* Bptr = W + (size_t)(nBase + lr) * HDIM + lc;
    for (int kt = 0; kt < HDIM; kt += 8) {
        float4 av = aok ? *(const float4*)(Aptr + kt) : make_float4(0, 0, 0, 0);
        float4 bv = *(const float4*)(Bptr + kt);
        As[lc + 0][lr] = av.x; As[lc + 1][lr] = av.y; As[lc + 2][lr] = av.z; As[lc + 3][lr] = av.w;
        Bs[lc + 0][lr] = bv.x; Bs[lc + 1][lr] = bv.y; Bs[lc + 2][lr] = bv.z; Bs[lc + 3][lr] = bv.w;
        __syncthreads();
#pragma unroll
        for (int kk = 0; kk < 8; ++kk) {
            float a[8], bfr[8];
            *(float4*)&a[0]   = *(const float4*)&As[kk][ty * 4];
            *(float4*)&a[4]   = *(const float4*)&As[kk][64 + ty * 4];
            *(float4*)&bfr[0] = *(const float4*)&Bs[kk][tx * 4];
            *(float4*)&bfr[4] = *(const float4*)&Bs[kk][64 + tx * 4];
#pragma unroll
            for (int i = 0; i < 8; ++i)
#pragma unroll
                for (int j = 0; j < 8; ++j) acc[i][j] += a[i] * bfr[j];
        }
        __syncthreads();
    }
    float fw = *fwp;
    int offs[BSEG];
#pragma unroll
    for (int b = 0; b < BSEG; ++b) offs[b] = __ldg(&offset[b]);
#pragma unroll
    for (int i = 0; i < 8; ++i) {
        int row = mBase + ((i < 4) ? (ty * 4 + i) : (64 + ty * 4 + i - 4));
        if (row >= M) continue;
        int b = 0;
#pragma unroll
        for (int q = 0; q < BSEG - 1; ++q)
            if (row >= offs[b]) ++b;
        const float* gv0 = &g_gate[b * CDIM + nBase + tx * 4];
        const float* gv1 = &g_gate[b * CDIM + nBase + 64 + tx * 4];
        const float4 f0 = *(const float4*)&feat[(size_t)row * CDIM + nBase + tx * 4];
        const float4 f1 = *(const float4*)&feat[(size_t)row * CDIM + nBase + 64 + tx * 4];
        float4 o0, o1;
        o0.x = f0.x + fw * gv0[0] * acc[i][0];
        o0.y = f0.y + fw * gv0[1] * acc[i][1];
        o0.z = f0.z + fw * gv0[2] * acc[i][2];
        o0.w = f0.w + fw * gv0[3] * acc[i][3];
        o1.x = f1.x + fw * gv1[0] * acc[i][4];
        o1.y = f1.y + fw * gv1[1] * acc[i][5];
        o1.z = f1.z + fw * gv1[2] * acc[i][6];
        o1.w = f1.w + fw * gv1[3] * acc[i][7];
        *(float4*)&out[(size_t)row * CDIM + nBase + tx * 4] = o0;
        *(float4*)&out[(size_t)row * CDIM + nBase + 64 + tx * 4] = o1;
    }
}

// ---------------- launch ----------------------------------------------------
extern "C" void kernel_launch(void* const* d_in, const int* in_sizes, int n_in,
                              void* d_out, int out_size) {
    const float* feat    = (const float*)d_in[0];
    const int*   offset  = (const int*)d_in[1];
    const float* norm_w  = (const float*)d_in[2];
    const float* norm_b  = (const float*)d_in[3];
    const float* in_proj = (const float*)d_in[4];
    const float* fwd_w   = (const float*)d_in[5];
    const float* bwd_w   = (const float*)d_in[6];
    const float* out_proj= (const float*)d_in[7];
    const float* gate_w  = (const float*)d_in[8];
    const float* fwp     = (const float*)d_in[9];
    float* out = (float*)d_out;

    int N = in_sizes[0] / CDIM;

    prep_kernel<<<20, 256>>>(fwd_w, bwd_w);
    reduce_kernel<<<dim3(512, BSEG), 256>>>(feat, offset);
    finalize_kernel<<<1, 32>>>(offset);
    norm_kernel<<<dim3(128, BSEG), 128>>>(feat, offset, norm_w, norm_b);
    gate_kernel<<<dim3(CDIM / 128, BSEG), 128>>>(gate_w, offset);
    gemm1_kernel<<<dim3(HDIM / 128, (N + 127) / 128), 256>>>(in_proj, N);
    conv_kernel<<<dim3(N, HDIM / 256), 256>>>(offset, N);
    gemm2_kernel<<<dim3(CDIM / 128, (N + 127) / 128), 256>>>(out_proj, feat, offset, fwp, out, N);
}

// round 3
// speedup vs baseline: 3.4011x; 3.4011x over previous
#include <cuda_runtime.h>
#include <cuda_bf16.h>
#include <math.h>
#include <stdint.h>

#define CDIM 512
#define HDIM 1024
#define KW 5
#define BSEG 8
#define EPSV 1e-5f
#define MAXN 24576

// ---------------- scratch (static device globals; no allocations) ----------
__device__ float g_sum[BSEG], g_sumsq[BSEG], g_mean[BSEG], g_rstd[BSEG];
__device__ float g_colsum[BSEG * CDIM];
__device__ float g_gate[BSEG * CDIM];
__device__ float g_wc[KW * HDIM];                       // combined dw weights (fp32)
__device__ __nv_bfloat16 g_xnb[(size_t)MAXN * CDIM];    // normalized feats bf16
__device__ __nv_bfloat16 g_state[(size_t)MAXN * HDIM];  // gelu(xn @ Win^T) bf16
__device__ __nv_bfloat16 g_mixed[(size_t)MAXN * HDIM];  // gelu(conv(state)) bf16
__device__ __nv_bfloat16 g_winb[HDIM * CDIM];           // W_in bf16
__device__ __nv_bfloat16 g_woutb[CDIM * HDIM];          // W_out bf16

__device__ __forceinline__ float gelu_exact(float x) {
    return 0.5f * x * (1.0f + erff(x * 0.7071067811865475f));
}

// ================= portable (sm_80+) async-copy / mma helpers ==============
__device__ __forceinline__ uint32_t smem_u32(const void* p) {
    uint32_t a;
    asm("{ .reg .u64 t; cvta.to.shared.u64 t, %1; cvt.u32.u64 %0, t; }"
        : "=r"(a) : "l"(p));
    return a;
}
__device__ __forceinline__ void cp_async16(uint32_t sm, const void* g) {
    asm volatile("cp.async.cg.shared.global [%0], [%1], 16;" :: "r"(sm), "l"(g));
}
__device__ __forceinline__ void cp_commit() {
    asm volatile("cp.async.commit_group;" ::: "memory");
}
template <int N>
__device__ __forceinline__ void cp_wait() {
    asm volatile("cp.async.wait_group %0;" :: "n"(N) : "memory");
}
__device__ __forceinline__ uint32_t sw128(uint32_t off) {
    return off ^ ((off >> 3) & 0x70);
}
__device__ __forceinline__ void ldmatrix_x4(uint32_t* r, uint32_t addr) {
    asm volatile("ldmatrix.sync.aligned.m8n8.x4.shared.b16 {%0,%1,%2,%3}, [%4];"
                 : "=r"(r[0]), "=r"(r[1]), "=r"(r[2]), "=r"(r[3]) : "r"(addr));
}
__device__ __forceinline__ void mma_bf16(float* c, const uint32_t* a, const uint32_t* b) {
    asm volatile(
        "mma.sync.aligned.m16n8k16.row.col.f32.bf16.bf16.f32 "
        "{%0,%1,%2,%3}, {%4,%5,%6,%7}, {%8,%9}, {%0,%1,%2,%3};"
        : "+f"(c[0]), "+f"(c[1]), "+f"(c[2]), "+f"(c[3])
        : "r"(a[0]), "r"(a[1]), "r"(a[2]), "r"(a[3]), "r"(b[0]), "r"(b[1]));
}

// GEMM geometry: 128x128 block, BK=64, 256 thr = 8 warps (2 M x 4 N), warp 64x32
#define BK 64
#define TILE_BYTES (128 * 128)   // 128 rows x 128B
#define SMEM_DYN (4 * TILE_BYTES + 1024)

// load one 128-row x 64-col bf16 chunk (A or B) into swizzled smem tile
__device__ __forceinline__ void load_tile(uint32_t dst, const __nv_bfloat16* src,
                                          int rowBase, int kOff, int K, int tid) {
    const char* base = (const char*)(src + (size_t)rowBase * K + kOff);
    size_t rowb = (size_t)K * 2;
#pragma unroll
    for (int i = 0; i < 4; ++i) {
        int idx = tid + i * 256;
        int r = idx >> 3, g = idx & 7;
        cp_async16(dst + sw128(r * 128 + g * 16), base + (size_t)r * rowb + g * 16);
    }
}

// compute one BK=64 chunk: 4 ksteps of 16
__device__ __forceinline__ void compute_chunk(float acc[4][4][4], uint32_t Abuf,
                                              uint32_t Bbuf, int lane, int wm, int wn) {
    int block = lane >> 3, l7 = lane & 7;
#pragma unroll
    for (int ks = 0; ks < 4; ++ks) {
        uint32_t a[4][4], br[4][2];
#pragma unroll
        for (int mi = 0; mi < 4; ++mi) {
            int arow = wm * 64 + mi * 16 + (block & 1) * 8 + l7;
            int akb = ks * 32 + (block >> 1) * 16;
            ldmatrix_x4(a[mi], Abuf + sw128(arow * 128 + akb));
        }
#pragma unroll
        for (int nb = 0; nb < 2; ++nb) {
            uint32_t r[4];
            int brow = wn * 32 + nb * 16 + (block >> 1) * 8 + l7;
            int bkb = ks * 32 + (block & 1) * 16;
            ldmatrix_x4(r, Bbuf + sw128(brow * 128 + bkb));
            br[nb * 2][0] = r[0]; br[nb * 2][1] = r[1];
            br[nb * 2 + 1][0] = r[2]; br[nb * 2 + 1][1] = r[3];
        }
#pragma unroll
        for (int mi = 0; mi < 4; ++mi)
#pragma unroll
            for (int ni = 0; ni < 4; ++ni)
                mma_bf16(acc[mi][ni], a[mi], br[ni]);
    }
}

// full mainloop: A[M,K] bf16, B[N,K] bf16, both K-contiguous
__device__ __forceinline__ void gemm_mainloop(float acc[4][4][4],
                                              const __nv_bfloat16* A,
                                              const __nv_bfloat16* Bw,
                                              int K, int nChunks, int mBase, int nBase,
                                              uint32_t sm) {
    int tid = threadIdx.x;
    int lane = tid & 31, warp = tid >> 5;
    int wm = warp >> 2, wn = warp & 3;
    uint32_t A0 = sm, B0 = sm + TILE_BYTES;
    uint32_t A1 = sm + 2 * TILE_BYTES, B1 = sm + 3 * TILE_BYTES;

    load_tile(A0, A, mBase, 0, K, tid);
    load_tile(B0, Bw, nBase, 0, K, tid);
    cp_commit();
    for (int c = 0; c < nChunks; ++c) {
        uint32_t Ab = (c & 1) ? A1 : A0;
        uint32_t Bb = (c & 1) ? B1 : B0;
        if (c + 1 < nChunks) {
            uint32_t An = (c & 1) ? A0 : A1;
            uint32_t Bn = (c & 1) ? B0 : B1;
            load_tile(An, A, mBase, (c + 1) * BK, K, tid);
            load_tile(Bn, Bw, nBase, (c + 1) * BK, K, tid);
            cp_commit();
            cp_wait<1>();
        } else {
            cp_wait<0>();
        }
        __syncthreads();
        compute_chunk(acc, Ab, Bb, lane, wm, wn);
        __syncthreads();
    }
}

// ---------------- prep kernels ---------------------------------------------
__global__ void prep_kernel(const float* __restrict__ fwd_w,
                            const float* __restrict__ bwd_w) {
    int i = blockIdx.x * blockDim.x + threadIdx.x;
    if (i < BSEG) { g_sum[i] = 0.f; g_sumsq[i] = 0.f; }
    if (i < BSEG * CDIM) g_colsum[i] = 0.f;
    if (i < KW * HDIM) {
        int k = i / HDIM, h = i % HDIM;
        g_wc[i] = 0.5f * (fwd_w[h * KW + k] + bwd_w[h * KW + (KW - 1 - k)]);
    }
}
__global__ void wconv_kernel(const float* __restrict__ win,
                             const float* __restrict__ wout) {
    int i = blockIdx.x * blockDim.x + threadIdx.x;
    if (i < HDIM * CDIM) {
        g_winb[i] = __float2bfloat16(win[i]);
        g_woutb[i] = __float2bfloat16(wout[i]);
    }
}

// ---------------- per-segment sum / sumsq ----------------------------------
__global__ void reduce_kernel(const float* __restrict__ feat,
                              const int* __restrict__ offset) {
    int b = blockIdx.y;
    int start = b ? offset[b - 1] : 0;
    long base4 = (long)start * (CDIM / 4);
    long end4 = (long)offset[b] * (CDIM / 4);
    const float4* f4 = (const float4*)feat;
    float s = 0.f, s2 = 0.f;
    long i = base4 + (long)blockIdx.x * (blockDim.x * 4) + threadIdx.x;
#pragma unroll
    for (int it = 0; it < 4; ++it) {
        if (i < end4) {
            float4 v = f4[i];
            s += v.x + v.y + v.z + v.w;
            s2 += v.x * v.x + v.y * v.y + v.z * v.z + v.w * v.w;
        }
        i += blockDim.x;
    }
    unsigned m = 0xffffffffu;
    for (int o = 16; o; o >>= 1) {
        s += __shfl_down_sync(m, s, o);
        s2 += __shfl_down_sync(m, s2, o);
    }
    __shared__ float sh[2][8];
    int lane = threadIdx.x & 31, w = threadIdx.x >> 5;
    if (lane == 0) { sh[0][w] = s; sh[1][w] = s2; }
    __syncthreads();
    if (w == 0) {
        s = lane < 8 ? sh[0][lane] : 0.f;
        s2 = lane < 8 ? sh[1][lane] : 0.f;
        for (int o = 4; o; o >>= 1) {
            s += __shfl_down_sync(m, s, o);
            s2 += __shfl_down_sync(m, s2, o);
        }
        if (lane == 0) { atomicAdd(&g_sum[b], s); atomicAdd(&g_sumsq[b], s2); }
    }
}

__global__ void finalize_kernel(const int* __restrict__ offset) {
    int b = threadIdx.x;
    if (b < BSEG) {
        int start = b ? offset[b - 1] : 0;
        int cnt = offset[b] - start;
        float denom = (float)cnt * (float)CDIM;
        float mean = g_sum[b] / denom;
        float var = g_sumsq[b] / denom - mean * mean;
        g_mean[b] = mean;
        g_rstd[b] = rsqrtf(var + EPSV);
    }
}

// ---------------- normalize (bf16 out) + column sums -----------------------
__global__ void norm_kernel(const float* __restrict__ feat,
                            const int* __restrict__ offset,
                            const float* __restrict__ nw,
                            const float* __restrict__ nb) {
    int b = blockIdx.y;
    int start = b ? offset[b - 1] : 0;
    int end = offset[b];
    int row0 = start + blockIdx.x * 32;
    if (row0 >= end) return;
    int tid = threadIdx.x;
    float4 w = ((const float4*)nw)[tid];
    float4 bb = ((const float4*)nb)[tid];
    float mean = g_mean[b], rstd = g_rstd[b];
    float4 acc = make_float4(0.f, 0.f, 0.f, 0.f);
    int rend = min(end, row0 + 32);
    for (int r = row0; r < rend; ++r) {
        float4 v = ((const float4*)feat)[(long)r * (CDIM / 4) + tid];
        float4 x;
        x.x = (v.x - mean) * rstd * w.x + bb.x;
        x.y = (v.y - mean) * rstd * w.y + bb.y;
        x.z = (v.z - mean) * rstd * w.z + bb.z;
        x.w = (v.w - mean) * rstd * w.w + bb.w;
        __nv_bfloat162 p0 = __floats2bfloat162_rn(x.x, x.y);
        __nv_bfloat162 p1 = __floats2bfloat162_rn(x.z, x.w);
        uint2 pk = make_uint2(*(uint32_t*)&p0, *(uint32_t*)&p1);
        *(uint2*)&g_xnb[(size_t)r * CDIM + tid * 4] = pk;
        acc.x += x.x; acc.y += x.y; acc.z += x.z; acc.w += x.w;
    }
    float* cs = &g_colsum[b * CDIM + tid * 4];
    atomicAdd(cs + 0, acc.x);
    atomicAdd(cs + 1, acc.y);
    atomicAdd(cs + 2, acc.z);
    atomicAdd(cs + 3, acc.w);
}

// ---------------- gate ------------------------------------------------------
__global__ void gate_kernel(const float* __restrict__ gw,
                            const int* __restrict__ offset) {
    __shared__ float ms[CDIM];
    int b = blockIdx.y;
    int start = b ? offset[b - 1] : 0;
    float inv = 1.0f / (float)(offset[b] - start);
    for (int i = threadIdx.x; i < CDIM; i += blockDim.x)
        ms[i] = g_colsum[b * CDIM + i] * inv;
    __syncthreads();
    int c = blockIdx.x * blockDim.x + threadIdx.x;
    const float4* gr = (const float4*)(gw + (size_t)c * CDIM);
    float acc = 0.f;
#pragma unroll 4
    for (int k = 0; k < CDIM / 4; ++k) {
        float4 v = gr[k];
        acc += v.x * ms[4 * k] + v.y * ms[4 * k + 1] + v.z * ms[4 * k + 2] + v.w * ms[4 * k + 3];
    }
    g_gate[b * CDIM + c] = 1.0f / (1.0f + expf(-acc));
}

// ---------------- GEMM1: state = gelu(xn @ Win^T), bf16 out ----------------
__global__ __launch_bounds__(256) void gemm1_kernel(int M) {
    extern __shared__ char smraw[];
    uint32_t sm = (smem_u32(smraw) + 1023) & ~1023u;
    int mBase = blockIdx.y * 128, nBase = blockIdx.x * 128;
    float acc[4][4][4];
#pragma unroll
    for (int i = 0; i < 4; ++i)
#pragma unroll
        for (int j = 0; j < 4; ++j)
#pragma unroll
            for (int k = 0; k < 4; ++k) acc[i][j][k] = 0.f;
    gemm_mainloop(acc, g_xnb, g_winb, CDIM, CDIM / BK, mBase, nBase, sm);

    int lane = threadIdx.x & 31, warp = threadIdx.x >> 5;
    int wm = warp >> 2, wn = warp & 3;
    int lr = lane >> 2, lc2 = (lane & 3) * 2;
#pragma unroll
    for (int mi = 0; mi < 4; ++mi) {
        int r0 = mBase + wm * 64 + mi * 16 + lr;
#pragma unroll
        for (int ni = 0; ni < 4; ++ni) {
            int n0 = nBase + wn * 32 + ni * 8 + lc2;
            if (r0 < M) {
                __nv_bfloat162 p = __floats2bfloat162_rn(gelu_exact(acc[mi][ni][0]),
                                                         gelu_exact(acc[mi][ni][1]));
                *(uint32_t*)&g_state[(size_t)r0 * HDIM + n0] = *(uint32_t*)&p;
            }
            if (r0 + 8 < M) {
                __nv_bfloat162 p = __floats2bfloat162_rn(gelu_exact(acc[mi][ni][2]),
                                                         gelu_exact(acc[mi][ni][3]));
                *(uint32_t*)&g_state[(size_t)(r0 + 8) * HDIM + n0] = *(uint32_t*)&p;
            }
        }
    }
}

// ---------------- depthwise conv (fwd+bwd combined) + gelu, bf16 -----------
__global__ __launch_bounds__(128) void conv_kernel(const int* __restrict__ offset, int N) {
    int n = blockIdx.x;
    int tid = threadIdx.x;
    int b = 0;
#pragma unroll
    for (int q = 0; q < BSEG - 1; ++q)
        b += (n >= __ldg(&offset[q]));
    int start = b ? __ldg(&offset[b - 1]) : 0;
    int end = __ldg(&offset[b]);
    int h = tid * 8;
    float acc[8] = {0.f, 0.f, 0.f, 0.f, 0.f, 0.f, 0.f, 0.f};
#pragma unroll
    for (int k = 0; k < KW; ++k) {
        int r = n - (KW / 2) + k;
        if (r >= start && r < end) {
            uint4 v = *(const uint4*)&g_state[(size_t)r * HDIM + h];
            const uint32_t* vw = (const uint32_t*)&v;
#pragma unroll
            for (int j = 0; j < 4; ++j) {
                __nv_bfloat162 p = *(__nv_bfloat162*)&vw[j];
                acc[2 * j] += __ldg(&g_wc[k * HDIM + h + 2 * j]) * __bfloat162float(p.x);
                acc[2 * j + 1] += __ldg(&g_wc[k * HDIM + h + 2 * j + 1]) * __bfloat162float(p.y);
            }
        }
    }
    __nv_bfloat162 q0 = __floats2bfloat162_rn(gelu_exact(acc[0]), gelu_exact(acc[1]));
    __nv_bfloat162 q1 = __floats2bfloat162_rn(gelu_exact(acc[2]), gelu_exact(acc[3]));
    __nv_bfloat162 q2 = __floats2bfloat162_rn(gelu_exact(acc[4]), gelu_exact(acc[5]));
    __nv_bfloat162 q3 = __floats2bfloat162_rn(gelu_exact(acc[6]), gelu_exact(acc[7]));
    uint4 o = make_uint4(*(uint32_t*)&q0, *(uint32_t*)&q1, *(uint32_t*)&q2, *(uint32_t*)&q3);
    *(uint4*)&g_mixed[(size_t)n * HDIM + h] = o;
}

// ---------------- GEMM2 + fused epilogue -----------------------------------
__global__ __launch_bounds__(256) void gemm2_kernel(const float* __restrict__ feat,
                                                    const int* __restrict__ offset,
                                                    const float* __restrict__ fwp,
                                                    float* __restrict__ out, int M) {
    extern __shared__ char smraw[];
    uint32_t sm = (smem_u32(smraw) + 1023) & ~1023u;
    int mBase = blockIdx.y * 128, nBase = blockIdx.x * 128;
    float acc[4][4][4];
#pragma unroll
    for (int i = 0; i < 4; ++i)
#pragma unroll
        for (int j = 0; j < 4; ++j)
#pragma unroll
            for (int k = 0; k < 4; ++k) acc[i][j][k] = 0.f;
    gemm_mainloop(acc, g_mixed, g_woutb, HDIM, HDIM / BK, mBase, nBase, sm);

    int lane = threadIdx.x & 31, warp = threadIdx.x >> 5;
    int wm = warp >> 2, wn = warp & 3;
    int lr = lane >> 2, lc2 = (lane & 3) * 2;
    float fw = __ldg(fwp);
    int offs[BSEG - 1];
#pragma unroll
    for (int q = 0; q < BSEG - 1; ++q) offs[q] = __ldg(&offset[q]);
#pragma unroll
    for (int mi = 0; mi < 4; ++mi) {
        int r0 = mBase + wm * 64 + mi * 16 + lr;
#pragma unroll
        for (int half = 0; half < 2; ++half) {
            int r = r0 + half * 8;
            if (r >= M) continue;
            int b = 0;
#pragma unroll
            for (int q = 0; q < BSEG - 1; ++q) b += (r >= offs[q]);
#pragma unroll
            for (int ni = 0; ni < 4; ++ni) {
                int n0 = nBase + wn * 32 + ni * 8 + lc2;
                float c0 = acc[mi][ni][2 * half], c1 = acc[mi][ni][2 * half + 1];
                float2 f = *(const float2*)&feat[(size_t)r * CDIM + n0];
                float g0 = g_gate[b * CDIM + n0], g1 = g_gate[b * CDIM + n0 + 1];
                float2 o;
                o.x = f.x + fw * g0 * c0;
                o.y = f.y + fw * g1 * c1;
                *(float2*)&out[(size_t)r * CDIM + n0] = o;
            }
        }
    }
}

// ---------------- launch ----------------------------------------------------
extern "C" void kernel_launch(void* const* d_in, const int* in_sizes, int n_in,
                              void* d_out, int out_size) {
    const float* feat = (const float*)d_in[0];
    const int* offset = (const int*)d_in[1];
    const float* norm_w = (const float*)d_in[2];
    const float* norm_b = (const float*)d_in[3];
    const float* in_proj = (const float*)d_in[4];
    const float* fwd_w = (const float*)d_in[5];
    const float* bwd_w = (const float*)d_in[6];
    const float* out_proj = (const float*)d_in[7];
    const float* gate_w = (const float*)d_in[8];
    const float* fwp = (const float*)d_in[9];
    float* out = (float*)d_out;

    int N = in_sizes[0] / CDIM;
    int MT = (N + 127) / 128;

    cudaFuncSetAttribute(gemm1_kernel, cudaFuncAttributeMaxDynamicSharedMemorySize, SMEM_DYN);
    cudaFuncSetAttribute(gemm2_kernel, cudaFuncAttributeMaxDynamicSharedMemorySize, SMEM_DYN);

    prep_kernel<<<20, 256>>>(fwd_w, bwd_w);
    wconv_kernel<<<2048, 256>>>(in_proj, out_proj);
    reduce_kernel<<<dim3(128, BSEG), 256>>>(feat, offset);
    finalize_kernel<<<1, 32>>>(offset);
    norm_kernel<<<dim3(128, BSEG), 128>>>(feat, offset, norm_w, norm_b);
    gate_kernel<<<dim3(CDIM / 128, BSEG), 128>>>(gate_w, offset);
    gemm1_kernel<<<dim3(HDIM / 128, MT), 256, SMEM_DYN>>>(N);
    conv_kernel<<<N, 128>>>(offset, N);
    gemm2_kernel<<<dim3(CDIM / 128, MT), 256, SMEM_DYN>>>(feat, offset, fwp, out, N);
}

// round 5
// speedup vs baseline: 4.0909x; 1.2028x over previous
#include <cuda_runtime.h>
#include <cuda_bf16.h>
#include <math.h>
#include <stdint.h>

#define CDIM 512
#define HDIM 1024
#define KW 5
#define BSEG 8
#define EPSV 1e-5f
#define MAXN 24576

// ---------------- scratch (static device globals; no allocations) ----------
__device__ float g_sum[BSEG], g_sumsq[BSEG];
__device__ float g_colsum[BSEG * CDIM];
__device__ float g_gate[BSEG * CDIM];
__device__ float g_wc[KW * HDIM];                       // combined dw weights (fp32)
__device__ __nv_bfloat16 g_xnb[(size_t)MAXN * CDIM];    // normalized feats bf16
__device__ __nv_bfloat16 g_state[(size_t)MAXN * HDIM];  // gelu(xn @ Win^T) bf16
__device__ __nv_bfloat16 g_mixed[(size_t)MAXN * HDIM];  // gelu(conv(state)) bf16
__device__ __nv_bfloat16 g_winb[HDIM * CDIM];           // W_in bf16
__device__ __nv_bfloat16 g_woutb[CDIM * HDIM];          // W_out bf16

__device__ __forceinline__ float gelu_exact(float x) {
    return 0.5f * x * (1.0f + erff(x * 0.7071067811865475f));
}

// ================= portable (sm_80+) async-copy / mma helpers ==============
__device__ __forceinline__ uint32_t smem_u32(const void* p) {
    uint32_t a;
    asm("{ .reg .u64 t; cvta.to.shared.u64 t, %1; cvt.u32.u64 %0, t; }"
        : "=r"(a) : "l"(p));
    return a;
}
__device__ __forceinline__ void cp_async16(uint32_t sm, const void* g) {
    asm volatile("cp.async.cg.shared.global [%0], [%1], 16;" :: "r"(sm), "l"(g));
}
__device__ __forceinline__ void cp_commit() {
    asm volatile("cp.async.commit_group;" ::: "memory");
}
template <int N>
__device__ __forceinline__ void cp_wait() {
    asm volatile("cp.async.wait_group %0;" :: "n"(N) : "memory");
}
__device__ __forceinline__ uint32_t sw128(uint32_t off) {
    return off ^ ((off >> 3) & 0x70);
}
__device__ __forceinline__ void ldmatrix_x4(uint32_t* r, uint32_t addr) {
    asm volatile("ldmatrix.sync.aligned.m8n8.x4.shared.b16 {%0,%1,%2,%3}, [%4];"
                 : "=r"(r[0]), "=r"(r[1]), "=r"(r[2]), "=r"(r[3]) : "r"(addr));
}
__device__ __forceinline__ void mma_bf16(float* c, const uint32_t* a, const uint32_t* b) {
    asm volatile(
        "mma.sync.aligned.m16n8k16.row.col.f32.bf16.bf16.f32 "
        "{%0,%1,%2,%3}, {%4,%5,%6,%7}, {%8,%9}, {%0,%1,%2,%3};"
        : "+f"(c[0]), "+f"(c[1]), "+f"(c[2]), "+f"(c[3])
        : "r"(a[0]), "r"(a[1]), "r"(a[2]), "r"(a[3]), "r"(b[0]), "r"(b[1]));
}

// GEMM geometry: 128x128 block, BK=64, 256 thr = 8 warps (2 M x 4 N), warp 64x32
#define BK 64
#define TILE_BYTES 16384           // 128 rows x 128B
#define STAGE_BYTES (2 * TILE_BYTES)
#define NSTAGES 3
#define SMEM_DYN (NSTAGES * STAGE_BYTES + 1024)

// load one 128-row x 64-col bf16 chunk (A or B) into swizzled smem tile
__device__ __forceinline__ void load_tile(uint32_t dst, const __nv_bfloat16* src,
                                          int rowBase, int kOff, int K, int tid) {
    const char* base = (const char*)(src + (size_t)rowBase * K + kOff);
    size_t rowb = (size_t)K * 2;
#pragma unroll
    for (int i = 0; i < 4; ++i) {
        int idx = tid + i * 256;
        int r = idx >> 3, g = idx & 7;
        cp_async16(dst + sw128(r * 128 + g * 16), base + (size_t)r * rowb + g * 16);
    }
}

// compute one BK=64 chunk: 4 ksteps of 16
__device__ __forceinline__ void compute_chunk(float acc[4][4][4], uint32_t Abuf,
                                              uint32_t Bbuf, int lane, int wm, int wn) {
    int block = lane >> 3, l7 = lane & 7;
#pragma unroll
    for (int ks = 0; ks < 4; ++ks) {
        uint32_t a[4][4], br[4][2];
#pragma unroll
        for (int mi = 0; mi < 4; ++mi) {
            int arow = wm * 64 + mi * 16 + (block & 1) * 8 + l7;
            int akb = ks * 32 + (block >> 1) * 16;
            ldmatrix_x4(a[mi], Abuf + sw128(arow * 128 + akb));
        }
#pragma unroll
        for (int nb = 0; nb < 2; ++nb) {
            uint32_t r[4];
            int brow = wn * 32 + nb * 16 + (block >> 1) * 8 + l7;
            int bkb = ks * 32 + (block & 1) * 16;
            ldmatrix_x4(r, Bbuf + sw128(brow * 128 + bkb));
            br[nb * 2][0] = r[0]; br[nb * 2][1] = r[1];
            br[nb * 2 + 1][0] = r[2]; br[nb * 2 + 1][1] = r[3];
        }
#pragma unroll
        for (int mi = 0; mi < 4; ++mi)
#pragma unroll
            for (int ni = 0; ni < 4; ++ni)
                mma_bf16(acc[mi][ni], a[mi], br[ni]);
    }
}

// 3-stage pipelined mainloop: A[M,K] bf16, B[N,K] bf16, both K-contiguous
__device__ __forceinline__ void gemm_mainloop(float acc[4][4][4],
                                              const __nv_bfloat16* A,
                                              const __nv_bfloat16* Bw,
                                              int K, int nChunks, int mBase, int nBase,
                                              uint32_t sm) {
    int tid = threadIdx.x;
    int lane = tid & 31, warp = tid >> 5;
    int wm = warp >> 2, wn = warp & 3;

    // prologue: issue chunks 0 and 1
#pragma unroll
    for (int s = 0; s < NSTAGES - 1; ++s) {
        load_tile(sm + s * STAGE_BYTES, A, mBase, s * BK, K, tid);
        load_tile(sm + s * STAGE_BYTES + TILE_BYTES, Bw, nBase, s * BK, K, tid);
        cp_commit();
    }

    int sc = 0;                      // stage of chunk c
    int sl = NSTAGES - 1;            // stage where chunk c+2 goes
    for (int c = 0; c < nChunks; ++c) {
        cp_wait<NSTAGES - 2>();      // chunk c resident
        __syncthreads();             // also guards reuse of stage sl (computed at c-1)
        int cn = c + NSTAGES - 1;
        if (cn < nChunks) {
            load_tile(sm + sl * STAGE_BYTES, A, mBase, cn * BK, K, tid);
            load_tile(sm + sl * STAGE_BYTES + TILE_BYTES, Bw, nBase, cn * BK, K, tid);
        }
        cp_commit();                 // commit (possibly empty) keeps group count aligned
        compute_chunk(acc, sm + sc * STAGE_BYTES, sm + sc * STAGE_BYTES + TILE_BYTES,
                      lane, wm, wn);
        sl = sc;
        sc = (sc + 1 == NSTAGES) ? 0 : sc + 1;
    }
}

// ---------------- prep: conv weights + bf16 weight conversion + zeroing -----
__global__ void prep_kernel(const float* __restrict__ fwd_w,
                            const float* __restrict__ bwd_w,
                            const float* __restrict__ win,
                            const float* __restrict__ wout) {
    int i = blockIdx.x * blockDim.x + threadIdx.x;
    if (i < BSEG) { g_sum[i] = 0.f; g_sumsq[i] = 0.f; }
    if (i < BSEG * CDIM) g_colsum[i] = 0.f;
    if (i < KW * HDIM) {
        int k = i / HDIM, h = i % HDIM;
        g_wc[i] = 0.5f * (fwd_w[h * KW + k] + bwd_w[h * KW + (KW - 1 - k)]);
    }
    if (i < HDIM * CDIM) {
        g_winb[i] = __float2bfloat16(win[i]);
        g_woutb[i] = __float2bfloat16(wout[i]);
    }
}

// ---------------- per-segment sum / sumsq ----------------------------------
__global__ void reduce_kernel(const float* __restrict__ feat,
                              const int* __restrict__ offset) {
    int b = blockIdx.y;
    int start = b ? offset[b - 1] : 0;
    long base4 = (long)start * (CDIM / 4);
    long end4 = (long)offset[b] * (CDIM / 4);
    const float4* f4 = (const float4*)feat;
    float s = 0.f, s2 = 0.f;
    long i = base4 + (long)blockIdx.x * (blockDim.x * 4) + threadIdx.x;
#pragma unroll
    for (int it = 0; it < 4; ++it) {
        if (i < end4) {
            float4 v = f4[i];
            s += v.x + v.y + v.z + v.w;
            s2 += v.x * v.x + v.y * v.y + v.z * v.z + v.w * v.w;
        }
        i += blockDim.x;
    }
    unsigned m = 0xffffffffu;
    for (int o = 16; o; o >>= 1) {
        s += __shfl_down_sync(m, s, o);
        s2 += __shfl_down_sync(m, s2, o);
    }
    __shared__ float sh[2][8];
    int lane = threadIdx.x & 31, w = threadIdx.x >> 5;
    if (lane == 0) { sh[0][w] = s; sh[1][w] = s2; }
    __syncthreads();
    if (w == 0) {
        s = lane < 8 ? sh[0][lane] : 0.f;
        s2 = lane < 8 ? sh[1][lane] : 0.f;
        for (int o = 4; o; o >>= 1) {
            s += __shfl_down_sync(m, s, o);
            s2 += __shfl_down_sync(m, s2, o);
        }
        if (lane == 0) { atomicAdd(&g_sum[b], s); atomicAdd(&g_sumsq[b], s2); }
    }
}

// ---------------- normalize (bf16 out) + column sums; inline finalize ------
__global__ void norm_kernel(const float* __restrict__ feat,
                            const int* __restrict__ offset,
                            const float* __restrict__ nw,
                            const float* __restrict__ nb) {
    int b = blockIdx.y;
    int start = b ? offset[b - 1] : 0;
    int end = offset[b];
    int row0 = start + blockIdx.x * 32;
    if (row0 >= end) return;
    // inline finalize: mean/rstd from reduced sums (cheap, per block)
    float denom = (float)(end - start) * (float)CDIM;
    float mean = g_sum[b] / denom;
    float var = g_sumsq[b] / denom - mean * mean;
    float rstd = rsqrtf(var + EPSV);
    int tid = threadIdx.x;
    float4 w = ((const float4*)nw)[tid];
    float4 bb = ((const float4*)nb)[tid];
    float4 acc = make_float4(0.f, 0.f, 0.f, 0.f);
    int rend = min(end, row0 + 32);
    for (int r = row0; r < rend; ++r) {
        float4 v = ((const float4*)feat)[(long)r * (CDIM / 4) + tid];
        float4 x;
        x.x = (v.x - mean) * rstd * w.x + bb.x;
        x.y = (v.y - mean) * rstd * w.y + bb.y;
        x.z = (v.z - mean) * rstd * w.z + bb.z;
        x.w = (v.w - mean) * rstd * w.w + bb.w;
        __nv_bfloat162 p0 = __floats2bfloat162_rn(x.x, x.y);
        __nv_bfloat162 p1 = __floats2bfloat162_rn(x.z, x.w);
        uint2 pk = make_uint2(*(uint32_t*)&p0, *(uint32_t*)&p1);
        *(uint2*)&g_xnb[(size_t)r * CDIM + tid * 4] = pk;
        acc.x += x.x; acc.y += x.y; acc.z += x.z; acc.w += x.w;
    }
    float* cs = &g_colsum[b * CDIM + tid * 4];
    atomicAdd(cs + 0, acc.x);
    atomicAdd(cs + 1, acc.y);
    atomicAdd(cs + 2, acc.z);
    atomicAdd(cs + 3, acc.w);
}

// ---------------- gate ------------------------------------------------------
__global__ void gate_kernel(const float* __restrict__ gw,
                            const int* __restrict__ offset) {
    __shared__ float ms[CDIM];
    int b = blockIdx.y;
    int start = b ? offset[b - 1] : 0;
    float inv = 1.0f / (float)(offset[b] - start);
    for (int i = threadIdx.x; i < CDIM; i += blockDim.x)
        ms[i] = g_colsum[b * CDIM + i] * inv;
    __syncthreads();
    int c = blockIdx.x * blockDim.x + threadIdx.x;
    const float4* gr = (const float4*)(gw + (size_t)c * CDIM);
    float acc = 0.f;
#pragma unroll 4
    for (int k = 0; k < CDIM / 4; ++k) {
        float4 v = gr[k];
        acc += v.x * ms[4 * k] + v.y * ms[4 * k + 1] + v.z * ms[4 * k + 2] + v.w * ms[4 * k + 3];
    }
    g_gate[b * CDIM + c] = 1.0f / (1.0f + expf(-acc));
}

// ---------------- GEMM1: state = gelu(xn @ Win^T), bf16 out ----------------
__global__ __launch_bounds__(256, 2) void gemm1_kernel(int M) {
    extern __shared__ char smraw[];
    uint32_t sm = (smem_u32(smraw) + 1023) & ~1023u;
    int mBase = blockIdx.y * 128, nBase = blockIdx.x * 128;
    float acc[4][4][4];
#pragma unroll
    for (int i = 0; i < 4; ++i)
#pragma unroll
        for (int j = 0; j < 4; ++j)
#pragma unroll
            for (int k = 0; k < 4; ++k) acc[i][j][k] = 0.f;
    gemm_mainloop(acc, g_xnb, g_winb, CDIM, CDIM / BK, mBase, nBase, sm);

    int lane = threadIdx.x & 31, warp = threadIdx.x >> 5;
    int wm = warp >> 2, wn = warp & 3;
    int lr = lane >> 2, lc2 = (lane & 3) * 2;
#pragma unroll
    for (int mi = 0; mi < 4; ++mi) {
        int r0 = mBase + wm * 64 + mi * 16 + lr;
#pragma unroll
        for (int ni = 0; ni < 4; ++ni) {
            int n0 = nBase + wn * 32 + ni * 8 + lc2;
            if (r0 < M) {
                __nv_bfloat162 p = __floats2bfloat162_rn(gelu_exact(acc[mi][ni][0]),
                                                         gelu_exact(acc[mi][ni][1]));
                *(uint32_t*)&g_state[(size_t)r0 * HDIM + n0] = *(uint32_t*)&p;
            }
            if (r0 + 8 < M) {
                __nv_bfloat162 p = __floats2bfloat162_rn(gelu_exact(acc[mi][ni][2]),
                                                         gelu_exact(acc[mi][ni][3]));
                *(uint32_t*)&g_state[(size_t)(r0 + 8) * HDIM + n0] = *(uint32_t*)&p;
            }
        }
    }
}

// ---------------- depthwise conv (fwd+bwd combined) + gelu, bf16 -----------
__global__ __launch_bounds__(128) void conv_kernel(const int* __restrict__ offset, int N) {
    int n = blockIdx.x;
    int tid = threadIdx.x;
    int b = 0;
#pragma unroll
    for (int q = 0; q < BSEG - 1; ++q)
        b += (n >= __ldg(&offset[q]));
    int start = b ? __ldg(&offset[b - 1]) : 0;
    int end = __ldg(&offset[b]);
    int h = tid * 8;
    float acc[8] = {0.f, 0.f, 0.f, 0.f, 0.f, 0.f, 0.f, 0.f};
#pragma unroll
    for (int k = 0; k < KW; ++k) {
        int r = n - (KW / 2) + k;
        if (r >= start && r < end) {
            uint4 v = *(const uint4*)&g_state[(size_t)r * HDIM + h];
            const uint32_t* vw = (const uint32_t*)&v;
#pragma unroll
            for (int j = 0; j < 4; ++j) {
                __nv_bfloat162 p = *(__nv_bfloat162*)&vw[j];
                acc[2 * j] += __ldg(&g_wc[k * HDIM + h + 2 * j]) * __bfloat162float(p.x);
                acc[2 * j + 1] += __ldg(&g_wc[k * HDIM + h + 2 * j + 1]) * __bfloat162float(p.y);
            }
        }
    }
    __nv_bfloat162 q0 = __floats2bfloat162_rn(gelu_exact(acc[0]), gelu_exact(acc[1]));
    __nv_bfloat162 q1 = __floats2bfloat162_rn(gelu_exact(acc[2]), gelu_exact(acc[3]));
    __nv_bfloat162 q2 = __floats2bfloat162_rn(gelu_exact(acc[4]), gelu_exact(acc[5]));
    __nv_bfloat162 q3 = __floats2bfloat162_rn(gelu_exact(acc[6]), gelu_exact(acc[7]));
    uint4 o = make_uint4(*(uint32_t*)&q0, *(uint32_t*)&q1, *(uint32_t*)&q2, *(uint32_t*)&q3);
    *(uint4*)&g_mixed[(size_t)n * HDIM + h] = o;
}

// ---------------- GEMM2 + fused epilogue -----------------------------------
__global__ __launch_bounds__(256, 2) void gemm2_kernel(const float* __restrict__ feat,
                                                       const int* __restrict__ offset,
                                                       const float* __restrict__ fwp,
                                                       float* __restrict__ out, int M) {
    extern __shared__ char smraw[];
    uint32_t sm = (smem_u32(smraw) + 1023) & ~1023u;
    int mBase = blockIdx.y * 128, nBase = blockIdx.x * 128;
    float acc[4][4][4];
#pragma unroll
    for (int i = 0; i < 4; ++i)
#pragma unroll
        for (int j = 0; j < 4; ++j)
#pragma unroll
            for (int k = 0; k < 4; ++k) acc[i][j][k] = 0.f;
    gemm_mainloop(acc, g_mixed, g_woutb, HDIM, HDIM / BK, mBase, nBase, sm);

    int lane = threadIdx.x & 31, warp = threadIdx.x >> 5;
    int wm = warp >> 2, wn = warp & 3;
    int lr = lane >> 2, lc2 = (lane & 3) * 2;
    float fw = __ldg(fwp);
    int offs[BSEG - 1];
#pragma unroll
    for (int q = 0; q < BSEG - 1; ++q) offs[q] = __ldg(&offset[q]);
#pragma unroll
    for (int mi = 0; mi < 4; ++mi) {
        int r0 = mBase + wm * 64 + mi * 16 + lr;
#pragma unroll
        for (int half = 0; half < 2; ++half) {
            int r = r0 + half * 8;
            if (r >= M) continue;
            int b = 0;
#pragma unroll
            for (int q = 0; q < BSEG - 1; ++q) b += (r >= offs[q]);
#pragma unroll
            for (int ni = 0; ni < 4; ++ni) {
                int n0 = nBase + wn * 32 + ni * 8 + lc2;
                float c0 = acc[mi][ni][2 * half], c1 = acc[mi][ni][2 * half + 1];
                float2 f = *(const float2*)&feat[(size_t)r * CDIM + n0];
                float g0 = g_gate[b * CDIM + n0], g1 = g_gate[b * CDIM + n0 + 1];
                float2 o;
                o.x = f.x + fw * g0 * c0;
                o.y = f.y + fw * g1 * c1;
                *(float2*)&out[(size_t)r * CDIM + n0] = o;
            }
        }
    }
}

// ---------------- launch ----------------------------------------------------
extern "C" void kernel_launch(void* const* d_in, const int* in_sizes, int n_in,
                              void* d_out, int out_size) {
    const float* feat = (const float*)d_in[0];
    const int* offset = (const int*)d_in[1];
    const float* norm_w = (const float*)d_in[2];
    const float* norm_b = (const float*)d_in[3];
    const float* in_proj = (const float*)d_in[4];
    const float* fwd_w = (const float*)d_in[5];
    const float* bwd_w = (const float*)d_in[6];
    const float* out_proj = (const float*)d_in[7];
    const float* gate_w = (const float*)d_in[8];
    const float* fwp = (const float*)d_in[9];
    float* out = (float*)d_out;

    int N = in_sizes[0] / CDIM;
    int MT = (N + 127) / 128;

    cudaFuncSetAttribute(gemm1_kernel, cudaFuncAttributeMaxDynamicSharedMemorySize, SMEM_DYN);
    cudaFuncSetAttribute(gemm2_kernel, cudaFuncAttributeMaxDynamicSharedMemorySize, SMEM_DYN);

    prep_kernel<<<(HDIM * CDIM + 255) / 256, 256>>>(fwd_w, bwd_w, in_proj, out_proj);
    reduce_kernel<<<dim3(128, BSEG), 256>>>(feat, offset);
    norm_kernel<<<dim3(128, BSEG), 128>>>(feat, offset, norm_w, norm_b);
    gate_kernel<<<dim3(CDIM / 128, BSEG), 128>>>(gate_w, offset);
    gemm1_kernel<<<dim3(HDIM / 128, MT), 256, SMEM_DYN>>>(N);
    conv_kernel<<<N, 128>>>(offset, N);
    gemm2_kernel<<<dim3(CDIM / 128, MT), 256, SMEM_DYN>>>(feat, offset, fwp, out, N);
}

// round 6
// speedup vs baseline: 4.0913x; 1.0001x over previous
#include <cuda_runtime.h>
#include <cuda_bf16.h>
#include <math.h>
#include <stdint.h>

#define CDIM 512
#define HDIM 1024
#define KW 5
#define BSEG 8
#define EPSV 1e-5f
#define MAXN 24576

// ---------------- scratch (static device globals; no allocations) ----------
__device__ float g_sum[BSEG], g_sumsq[BSEG];
__device__ float g_colsum[BSEG * CDIM];
__device__ float g_gate[BSEG * CDIM];
__device__ float g_wc[KW * HDIM];                       // combined dw weights (fp32)
__device__ __nv_bfloat16 g_xnb[(size_t)MAXN * CDIM];    // normalized feats bf16
__device__ __nv_bfloat16 g_state[(size_t)MAXN * HDIM];  // gelu(xn @ Win^T) bf16
__device__ __nv_bfloat16 g_mixed[(size_t)MAXN * HDIM];  // gelu(conv(state)) bf16
__device__ __nv_bfloat16 g_winb[HDIM * CDIM];           // W_in bf16
__device__ __nv_bfloat16 g_woutb[CDIM * HDIM];          // W_out bf16

__device__ __forceinline__ float gelu_exact(float x) {
    return 0.5f * x * (1.0f + erff(x * 0.7071067811865475f));
}

// ================= portable (sm_80+) async-copy / mma helpers ==============
__device__ __forceinline__ uint32_t smem_u32(const void* p) {
    uint32_t a;
    asm("{ .reg .u64 t; cvta.to.shared.u64 t, %1; cvt.u32.u64 %0, t; }"
        : "=r"(a) : "l"(p));
    return a;
}
__device__ __forceinline__ void cp_async16(uint32_t sm, const void* g) {
    asm volatile("cp.async.cg.shared.global [%0], [%1], 16;" :: "r"(sm), "l"(g));
}
__device__ __forceinline__ void cp_commit() {
    asm volatile("cp.async.commit_group;" ::: "memory");
}
template <int N>
__device__ __forceinline__ void cp_wait() {
    asm volatile("cp.async.wait_group %0;" :: "n"(N) : "memory");
}
__device__ __forceinline__ uint32_t sw128(uint32_t off) {
    return off ^ ((off >> 3) & 0x70);
}
__device__ __forceinline__ void ldmatrix_x4(uint32_t* r, uint32_t addr) {
    asm volatile("ldmatrix.sync.aligned.m8n8.x4.shared.b16 {%0,%1,%2,%3}, [%4];"
                 : "=r"(r[0]), "=r"(r[1]), "=r"(r[2]), "=r"(r[3]) : "r"(addr));
}
__device__ __forceinline__ void mma_bf16(float* c, const uint32_t* a, const uint32_t* b) {
    asm volatile(
        "mma.sync.aligned.m16n8k16.row.col.f32.bf16.bf16.f32 "
        "{%0,%1,%2,%3}, {%4,%5,%6,%7}, {%8,%9}, {%0,%1,%2,%3};"
        : "+f"(c[0]), "+f"(c[1]), "+f"(c[2]), "+f"(c[3])
        : "r"(a[0]), "r"(a[1]), "r"(a[2]), "r"(a[3]), "r"(b[0]), "r"(b[1]));
}

// GEMM geometry: 128x128 block, BK=64, 256 thr = 8 warps (2 M x 4 N), warp 64x32
#define BK 64
#define TILE_BYTES 16384           // 128 rows x 128B
#define STAGE_BYTES (2 * TILE_BYTES)
#define NSTAGES 3
#define SMEM_DYN (NSTAGES * STAGE_BYTES + 1024)

// load one 128-row x 64-col bf16 chunk (A or B) into swizzled smem tile
__device__ __forceinline__ void load_tile(uint32_t dst, const __nv_bfloat16* src,
                                          int rowBase, int kOff, int K, int tid) {
    const char* base = (const char*)(src + (size_t)rowBase * K + kOff);
    size_t rowb = (size_t)K * 2;
#pragma unroll
    for (int i = 0; i < 4; ++i) {
        int idx = tid + i * 256;
        int r = idx >> 3, g = idx & 7;
        cp_async16(dst + sw128(r * 128 + g * 16), base + (size_t)r * rowb + g * 16);
    }
}

// compute one BK=64 chunk: 4 ksteps of 16
__device__ __forceinline__ void compute_chunk(float acc[4][4][4], uint32_t Abuf,
                                              uint32_t Bbuf, int lane, int wm, int wn) {
    int block = lane >> 3, l7 = lane & 7;
#pragma unroll
    for (int ks = 0; ks < 4; ++ks) {
        uint32_t a[4][4], br[4][2];
#pragma unroll
        for (int mi = 0; mi < 4; ++mi) {
            int arow = wm * 64 + mi * 16 + (block & 1) * 8 + l7;
            int akb = ks * 32 + (block >> 1) * 16;
            ldmatrix_x4(a[mi], Abuf + sw128(arow * 128 + akb));
        }
#pragma unroll
        for (int nb = 0; nb < 2; ++nb) {
            uint32_t r[4];
            int brow = wn * 32 + nb * 16 + (block >> 1) * 8 + l7;
            int bkb = ks * 32 + (block & 1) * 16;
            ldmatrix_x4(r, Bbuf + sw128(brow * 128 + bkb));
            br[nb * 2][0] = r[0]; br[nb * 2][1] = r[1];
            br[nb * 2 + 1][0] = r[2]; br[nb * 2 + 1][1] = r[3];
        }
#pragma unroll
        for (int mi = 0; mi < 4; ++mi)
#pragma unroll
            for (int ni = 0; ni < 4; ++ni)
                mma_bf16(acc[mi][ni], a[mi], br[ni]);
    }
}

// 3-stage pipelined mainloop: A[M,K] bf16, B[N,K] bf16, both K-contiguous
__device__ __forceinline__ void gemm_mainloop(float acc[4][4][4],
                                              const __nv_bfloat16* A,
                                              const __nv_bfloat16* Bw,
                                              int K, int nChunks, int mBase, int nBase,
                                              uint32_t sm) {
    int tid = threadIdx.x;
    int lane = tid & 31, warp = tid >> 5;
    int wm = warp >> 2, wn = warp & 3;

    // prologue: issue chunks 0 and 1
#pragma unroll
    for (int s = 0; s < NSTAGES - 1; ++s) {
        load_tile(sm + s * STAGE_BYTES, A, mBase, s * BK, K, tid);
        load_tile(sm + s * STAGE_BYTES + TILE_BYTES, Bw, nBase, s * BK, K, tid);
        cp_commit();
    }

    int sc = 0;                      // stage of chunk c
    int sl = NSTAGES - 1;            // stage where chunk c+2 goes
    for (int c = 0; c < nChunks; ++c) {
        cp_wait<NSTAGES - 2>();      // chunk c resident
        __syncthreads();             // also guards reuse of stage sl (computed at c-1)
        int cn = c + NSTAGES - 1;
        if (cn < nChunks) {
            load_tile(sm + sl * STAGE_BYTES, A, mBase, cn * BK, K, tid);
            load_tile(sm + sl * STAGE_BYTES + TILE_BYTES, Bw, nBase, cn * BK, K, tid);
        }
        cp_commit();                 // commit (possibly empty) keeps group count aligned
        compute_chunk(acc, sm + sc * STAGE_BYTES, sm + sc * STAGE_BYTES + TILE_BYTES,
                      lane, wm, wn);
        sl = sc;
        sc = (sc + 1 == NSTAGES) ? 0 : sc + 1;
    }
}

// ---------------- prep: conv weights + bf16 weight conversion + zeroing -----
__global__ void prep_kernel(const float* __restrict__ fwd_w,
                            const float* __restrict__ bwd_w,
                            const float* __restrict__ win,
                            const float* __restrict__ wout) {
    int i = blockIdx.x * blockDim.x + threadIdx.x;
    if (i < BSEG) { g_sum[i] = 0.f; g_sumsq[i] = 0.f; }
    if (i < BSEG * CDIM) g_colsum[i] = 0.f;
    if (i < KW * HDIM) {
        int k = i / HDIM, h = i % HDIM;
        g_wc[i] = 0.5f * (fwd_w[h * KW + k] + bwd_w[h * KW + (KW - 1 - k)]);
    }
    if (i < HDIM * CDIM) {
        g_winb[i] = __float2bfloat16(win[i]);
        g_woutb[i] = __float2bfloat16(wout[i]);
    }
}

// ---------------- per-segment sum / sumsq ----------------------------------
__global__ void reduce_kernel(const float* __restrict__ feat,
                              const int* __restrict__ offset) {
    int b = blockIdx.y;
    int start = b ? offset[b - 1] : 0;
    long base4 = (long)start * (CDIM / 4);
    long end4 = (long)offset[b] * (CDIM / 4);
    const float4* f4 = (const float4*)feat;
    float s = 0.f, s2 = 0.f;
    long i = base4 + (long)blockIdx.x * (blockDim.x * 4) + threadIdx.x;
#pragma unroll
    for (int it = 0; it < 4; ++it) {
        if (i < end4) {
            float4 v = f4[i];
            s += v.x + v.y + v.z + v.w;
            s2 += v.x * v.x + v.y * v.y + v.z * v.z + v.w * v.w;
        }
        i += blockDim.x;
    }
    unsigned m = 0xffffffffu;
    for (int o = 16; o; o >>= 1) {
        s += __shfl_down_sync(m, s, o);
        s2 += __shfl_down_sync(m, s2, o);
    }
    __shared__ float sh[2][8];
    int lane = threadIdx.x & 31, w = threadIdx.x >> 5;
    if (lane == 0) { sh[0][w] = s; sh[1][w] = s2; }
    __syncthreads();
    if (w == 0) {
        s = lane < 8 ? sh[0][lane] : 0.f;
        s2 = lane < 8 ? sh[1][lane] : 0.f;
        for (int o = 4; o; o >>= 1) {
            s += __shfl_down_sync(m, s, o);
            s2 += __shfl_down_sync(m, s2, o);
        }
        if (lane == 0) { atomicAdd(&g_sum[b], s); atomicAdd(&g_sumsq[b], s2); }
    }
}

// ---------------- normalize (bf16 out) + column sums; inline finalize ------
__global__ void norm_kernel(const float* __restrict__ feat,
                            const int* __restrict__ offset,
                            const float* __restrict__ nw,
                            const float* __restrict__ nb) {
    int b = blockIdx.y;
    int start = b ? offset[b - 1] : 0;
    int end = offset[b];
    int row0 = start + blockIdx.x * 32;
    if (row0 >= end) return;
    // inline finalize: mean/rstd from reduced sums (cheap, per block)
    float denom = (float)(end - start) * (float)CDIM;
    float mean = g_sum[b] / denom;
    float var = g_sumsq[b] / denom - mean * mean;
    float rstd = rsqrtf(var + EPSV);
    int tid = threadIdx.x;
    float4 w = ((const float4*)nw)[tid];
    float4 bb = ((const float4*)nb)[tid];
    float4 acc = make_float4(0.f, 0.f, 0.f, 0.f);
    int rend = min(end, row0 + 32);
    for (int r = row0; r < rend; ++r) {
        float4 v = ((const float4*)feat)[(long)r * (CDIM / 4) + tid];
        float4 x;
        x.x = (v.x - mean) * rstd * w.x + bb.x;
        x.y = (v.y - mean) * rstd * w.y + bb.y;
        x.z = (v.z - mean) * rstd * w.z + bb.z;
        x.w = (v.w - mean) * rstd * w.w + bb.w;
        __nv_bfloat162 p0 = __floats2bfloat162_rn(x.x, x.y);
        __nv_bfloat162 p1 = __floats2bfloat162_rn(x.z, x.w);
        uint2 pk = make_uint2(*(uint32_t*)&p0, *(uint32_t*)&p1);
        *(uint2*)&g_xnb[(size_t)r * CDIM + tid * 4] = pk;
        acc.x += x.x; acc.y += x.y; acc.z += x.z; acc.w += x.w;
    }
    float* cs = &g_colsum[b * CDIM + tid * 4];
    atomicAdd(cs + 0, acc.x);
    atomicAdd(cs + 1, acc.y);
    atomicAdd(cs + 2, acc.z);
    atomicAdd(cs + 3, acc.w);
}

// ---------------- gate ------------------------------------------------------
__global__ void gate_kernel(const float* __restrict__ gw,
                            const int* __restrict__ offset) {
    __shared__ float ms[CDIM];
    int b = blockIdx.y;
    int start = b ? offset[b - 1] : 0;
    float inv = 1.0f / (float)(offset[b] - start);
    for (int i = threadIdx.x; i < CDIM; i += blockDim.x)
        ms[i] = g_colsum[b * CDIM + i] * inv;
    __syncthreads();
    int c = blockIdx.x * blockDim.x + threadIdx.x;
    const float4* gr = (const float4*)(gw + (size_t)c * CDIM);
    float acc = 0.f;
#pragma unroll 4
    for (int k = 0; k < CDIM / 4; ++k) {
        float4 v = gr[k];
        acc += v.x * ms[4 * k] + v.y * ms[4 * k + 1] + v.z * ms[4 * k + 2] + v.w * ms[4 * k + 3];
    }
    g_gate[b * CDIM + c] = 1.0f / (1.0f + expf(-acc));
}

// ---------------- GEMM1: state = gelu(xn @ Win^T), bf16 out ----------------
__global__ __launch_bounds__(256, 2) void gemm1_kernel(int M) {
    extern __shared__ char smraw[];
    uint32_t sm = (smem_u32(smraw) + 1023) & ~1023u;
    int mBase = blockIdx.y * 128, nBase = blockIdx.x * 128;
    float acc[4][4][4];
#pragma unroll
    for (int i = 0; i < 4; ++i)
#pragma unroll
        for (int j = 0; j < 4; ++j)
#pragma unroll
            for (int k = 0; k < 4; ++k) acc[i][j][k] = 0.f;
    gemm_mainloop(acc, g_xnb, g_winb, CDIM, CDIM / BK, mBase, nBase, sm);

    int lane = threadIdx.x & 31, warp = threadIdx.x >> 5;
    int wm = warp >> 2, wn = warp & 3;
    int lr = lane >> 2, lc2 = (lane & 3) * 2;
#pragma unroll
    for (int mi = 0; mi < 4; ++mi) {
        int r0 = mBase + wm * 64 + mi * 16 + lr;
#pragma unroll
        for (int ni = 0; ni < 4; ++ni) {
            int n0 = nBase + wn * 32 + ni * 8 + lc2;
            if (r0 < M) {
                __nv_bfloat162 p = __floats2bfloat162_rn(gelu_exact(acc[mi][ni][0]),
                                                         gelu_exact(acc[mi][ni][1]));
                *(uint32_t*)&g_state[(size_t)r0 * HDIM + n0] = *(uint32_t*)&p;
            }
            if (r0 + 8 < M) {
                __nv_bfloat162 p = __floats2bfloat162_rn(gelu_exact(acc[mi][ni][2]),
                                                         gelu_exact(acc[mi][ni][3]));
                *(uint32_t*)&g_state[(size_t)(r0 + 8) * HDIM + n0] = *(uint32_t*)&p;
            }
        }
    }
}

// ---------------- depthwise conv (fwd+bwd combined) + gelu, bf16 -----------
__global__ __launch_bounds__(128) void conv_kernel(const int* __restrict__ offset, int N) {
    int n = blockIdx.x;
    int tid = threadIdx.x;
    int b = 0;
#pragma unroll
    for (int q = 0; q < BSEG - 1; ++q)
        b += (n >= __ldg(&offset[q]));
    int start = b ? __ldg(&offset[b - 1]) : 0;
    int end = __ldg(&offset[b]);
    int h = tid * 8;
    float acc[8] = {0.f, 0.f, 0.f, 0.f, 0.f, 0.f, 0.f, 0.f};
#pragma unroll
    for (int k = 0; k < KW; ++k) {
        int r = n - (KW / 2) + k;
        if (r >= start && r < end) {
            uint4 v = *(const uint4*)&g_state[(size_t)r * HDIM + h];
            const uint32_t* vw = (const uint32_t*)&v;
#pragma unroll
            for (int j = 0; j < 4; ++j) {
                __nv_bfloat162 p = *(__nv_bfloat162*)&vw[j];
                acc[2 * j] += __ldg(&g_wc[k * HDIM + h + 2 * j]) * __bfloat162float(p.x);
                acc[2 * j + 1] += __ldg(&g_wc[k * HDIM + h + 2 * j + 1]) * __bfloat162float(p.y);
            }
        }
    }
    __nv_bfloat162 q0 = __floats2bfloat162_rn(gelu_exact(acc[0]), gelu_exact(acc[1]));
    __nv_bfloat162 q1 = __floats2bfloat162_rn(gelu_exact(acc[2]), gelu_exact(acc[3]));
    __nv_bfloat162 q2 = __floats2bfloat162_rn(gelu_exact(acc[4]), gelu_exact(acc[5]));
    __nv_bfloat162 q3 = __floats2bfloat162_rn(gelu_exact(acc[6]), gelu_exact(acc[7]));
    uint4 o = make_uint4(*(uint32_t*)&q0, *(uint32_t*)&q1, *(uint32_t*)&q2, *(uint32_t*)&q3);
    *(uint4*)&g_mixed[(size_t)n * HDIM + h] = o;
}

// ---------------- GEMM2 + fused epilogue -----------------------------------
__global__ __launch_bounds__(256, 2) void gemm2_kernel(const float* __restrict__ feat,
                                                       const int* __restrict__ offset,
                                                       const float* __restrict__ fwp,
                                                       float* __restrict__ out, int M) {
    extern __shared__ char smraw[];
    uint32_t sm = (smem_u32(smraw) + 1023) & ~1023u;
    int mBase = blockIdx.y * 128, nBase = blockIdx.x * 128;
    float acc[4][4][4];
#pragma unroll
    for (int i = 0; i < 4; ++i)
#pragma unroll
        for (int j = 0; j < 4; ++j)
#pragma unroll
            for (int k = 0; k < 4; ++k) acc[i][j][k] = 0.f;
    gemm_mainloop(acc, g_mixed, g_woutb, HDIM, HDIM / BK, mBase, nBase, sm);

    int lane = threadIdx.x & 31, warp = threadIdx.x >> 5;
    int wm = warp >> 2, wn = warp & 3;
    int lr = lane >> 2, lc2 = (lane & 3) * 2;
    float fw = __ldg(fwp);
    int offs[BSEG - 1];
#pragma unroll
    for (int q = 0; q < BSEG - 1; ++q) offs[q] = __ldg(&offset[q]);
#pragma unroll
    for (int mi = 0; mi < 4; ++mi) {
        int r0 = mBase + wm * 64 + mi * 16 + lr;
#pragma unroll
        for (int half = 0; half < 2; ++half) {
            int r = r0 + half * 8;
            if (r >= M) continue;
            int b = 0;
#pragma unroll
            for (int q = 0; q < BSEG - 1; ++q) b += (r >= offs[q]);
#pragma unroll
            for (int ni = 0; ni < 4; ++ni) {
                int n0 = nBase + wn * 32 + ni * 8 + lc2;
                float c0 = acc[mi][ni][2 * half], c1 = acc[mi][ni][2 * half + 1];
                float2 f = *(const float2*)&feat[(size_t)r * CDIM + n0];
                float g0 = g_gate[b * CDIM + n0], g1 = g_gate[b * CDIM + n0 + 1];
                float2 o;
                o.x = f.x + fw * g0 * c0;
                o.y = f.y + fw * g1 * c1;
                *(float2*)&out[(size_t)r * CDIM + n0] = o;
            }
        }
    }
}

// ---------------- launch ----------------------------------------------------
extern "C" void kernel_launch(void* const* d_in, const int* in_sizes, int n_in,
                              void* d_out, int out_size) {
    const float* feat = (const float*)d_in[0];
    const int* offset = (const int*)d_in[1];
    const float* norm_w = (const float*)d_in[2];
    const float* norm_b = (const float*)d_in[3];
    const float* in_proj = (const float*)d_in[4];
    const float* fwd_w = (const float*)d_in[5];
    const float* bwd_w = (const float*)d_in[6];
    const float* out_proj = (const float*)d_in[7];
    const float* gate_w = (const float*)d_in[8];
    const float* fwp = (const float*)d_in[9];
    float* out = (float*)d_out;

    int N = in_sizes[0] / CDIM;
    int MT = (N + 127) / 128;

    cudaFuncSetAttribute(gemm1_kernel, cudaFuncAttributeMaxDynamicSharedMemorySize, SMEM_DYN);
    cudaFuncSetAttribute(gemm2_kernel, cudaFuncAttributeMaxDynamicSharedMemorySize, SMEM_DYN);

    prep_kernel<<<(HDIM * CDIM + 255) / 256, 256>>>(fwd_w, bwd_w, in_proj, out_proj);
    reduce_kernel<<<dim3(128, BSEG), 256>>>(feat, offset);
    norm_kernel<<<dim3(128, BSEG), 128>>>(feat, offset, norm_w, norm_b);
    gate_kernel<<<dim3(CDIM / 128, BSEG), 128>>>(gate_w, offset);
    gemm1_kernel<<<dim3(HDIM / 128, MT), 256, SMEM_DYN>>>(N);
    conv_kernel<<<N, 128>>>(offset, N);
    gemm2_kernel<<<dim3(CDIM / 128, MT), 256, SMEM_DYN>>>(feat, offset, fwp, out, N);
}